// round 9
// baseline (speedup 1.0000x reference)
#include <cuda_runtime.h>
#include <math.h>

#define T_TOK 4096   // B*S
#define D_DIM 1024
#define E_NUM 8
#define H_DIM 4096
#define CAP   4096
#define MAXTILE 72

// ---- static scratch ----
__device__ float g_hbuf[(size_t)E_NUM * CAP * H_DIM];   // tf32-rounded h
__device__ float g_xt[(size_t)T_TOK * D_DIM];           // tf32-rounded x
__device__ int   g_counts[E_NUM];
__device__ int   g_list[E_NUM * CAP];
__device__ float g_gate[E_NUM * CAP];
__device__ int   g_tilemap[MAXTILE];
__device__ int   g_ntiles;

__global__ void zero_counts_kernel() {
    if (threadIdx.x < E_NUM) g_counts[threadIdx.x] = 0;
}

// zero the 'final' output region (poisoned by harness; gemm2 atomicAdds into it)
__global__ void zero_out_kernel(float* __restrict__ out) {
    size_t i = (size_t)blockIdx.x * blockDim.x + threadIdx.x;
    ((float4*)out)[i] = make_float4(0.f, 0.f, 0.f, 0.f);
}

__device__ __forceinline__ unsigned cvt_tf32(float f) {
    unsigned o;
    asm volatile("cvt.rna.tf32.f32 %0, %1;\n" : "=r"(o) : "f"(f));
    return o;
}

// ---------------- Router: one warp per token ----------------
// fp32 fast path; fp64 re-check only when the top2/top3 margin is tiny.
__global__ void router_kernel(const float* __restrict__ x,
                              const float* __restrict__ noise,
                              const float* __restrict__ Wr, const float* __restrict__ br,
                              const float* __restrict__ Wn, const float* __restrict__ bn,
                              float* __restrict__ gate_out /* [T,E] */) {
    int warp = (blockIdx.x * blockDim.x + threadIdx.x) >> 5;
    int lane = threadIdx.x & 31;
    if (warp >= T_TOK) return;

    const float* xr = x + (size_t)warp * D_DIM;
    float* xtr = g_xt + (size_t)warp * D_DIM;
    float aR[8], aN[8];
#pragma unroll
    for (int e = 0; e < 8; e++) { aR[e] = 0.f; aN[e] = 0.f; }

    for (int d0 = lane * 4; d0 < D_DIM; d0 += 32 * 4) {
        float4 xv = *(const float4*)(xr + d0);
        float4 xt;
        xt.x = __uint_as_float(cvt_tf32(xv.x));
        xt.y = __uint_as_float(cvt_tf32(xv.y));
        xt.z = __uint_as_float(cvt_tf32(xv.z));
        xt.w = __uint_as_float(cvt_tf32(xv.w));
        *(float4*)(xtr + d0) = xt;
        float xs[4] = {xv.x, xv.y, xv.z, xv.w};
#pragma unroll
        for (int u = 0; u < 4; ++u) {
            float xd = xs[u];
            const float4* wr = (const float4*)(Wr + (size_t)(d0 + u) * E_NUM);
            float4 r0 = wr[0], r1 = wr[1];
            const float4* wn = (const float4*)(Wn + (size_t)(d0 + u) * E_NUM);
            float4 q0 = wn[0], q1 = wn[1];
            aR[0] += xd * r0.x; aR[1] += xd * r0.y; aR[2] += xd * r0.z; aR[3] += xd * r0.w;
            aR[4] += xd * r1.x; aR[5] += xd * r1.y; aR[6] += xd * r1.z; aR[7] += xd * r1.w;
            aN[0] += xd * q0.x; aN[1] += xd * q0.y; aN[2] += xd * q0.z; aN[3] += xd * q0.w;
            aN[4] += xd * q1.x; aN[5] += xd * q1.y; aN[6] += xd * q1.z; aN[7] += xd * q1.w;
        }
    }
#pragma unroll
    for (int off = 16; off > 0; off >>= 1) {
#pragma unroll
        for (int e = 0; e < 8; e++) {
            aR[e] += __shfl_xor_sync(0xffffffffu, aR[e], off);
            aN[e] += __shfl_xor_sync(0xffffffffu, aN[e], off);
        }
    }

    if (lane == 0) {
        float lg[8], noisy[8];
#pragma unroll
        for (int e = 0; e < 8; e++) {
            lg[e] = aR[e] + br[e];
            float nl = aN[e] + bn[e];
            float sp = (nl > 20.f) ? nl : log1pf(expf(nl));
            noisy[e] = lg[e] + noise[(size_t)warp * E_NUM + e] * sp;
        }
        // top-3 (first occurrence wins ties)
        int i1 = 0;
#pragma unroll
        for (int e = 1; e < 8; e++) if (noisy[e] > noisy[i1]) i1 = e;
        int i2 = -1;
#pragma unroll
        for (int e = 0; e < 8; e++) {
            if (e == i1) continue;
            if (i2 < 0 || noisy[e] > noisy[i2]) i2 = e;
        }
        int i3 = -1;
#pragma unroll
        for (int e = 0; e < 8; e++) {
            if (e == i1 || e == i2) continue;
            if (i3 < 0 || noisy[e] > noisy[i3]) i3 = e;
        }
        float gap = noisy[i2] - noisy[i3];
        float d12 = noisy[i1] - noisy[i2];
        if (gap < 1e-3f) {
            // borderline selection: redo with exact fp64 softplus
            double nd[8];
#pragma unroll
            for (int e = 0; e < 8; e++) {
                double nl = (double)aN[e] + (double)bn[e];
                double sp = log1p(exp(nl));
                nd[e] = (double)lg[e] + (double)noise[(size_t)warp * E_NUM + e] * sp;
            }
            i1 = 0;
#pragma unroll
            for (int e = 1; e < 8; e++) if (nd[e] > nd[i1]) i1 = e;
            i2 = -1;
#pragma unroll
            for (int e = 0; e < 8; e++) {
                if (e == i1) continue;
                if (i2 < 0 || nd[e] > nd[i2]) i2 = e;
            }
            d12 = (float)(nd[i1] - nd[i2]);
        }
        float e2 = expf(-d12);
        float s = 1.0f + e2;
        float g1 = 1.0f / s, g2 = e2 / s;

        // dense softmax over plain logits
        float lm = lg[0];
#pragma unroll
        for (int e = 1; e < 8; e++) lm = fmaxf(lm, lg[e]);
        float se = 0.f, ex[8];
#pragma unroll
        for (int e = 0; e < 8; e++) { ex[e] = expf(lg[e] - lm); se += ex[e]; }
#pragma unroll
        for (int e = 0; e < 8; e++)
            gate_out[(size_t)warp * E_NUM + e] = ex[e] / se;

        int s1 = atomicAdd(&g_counts[i1], 1);
        g_list[i1 * CAP + s1] = warp;
        g_gate[i1 * CAP + s1] = g1;
        int s2 = atomicAdd(&g_counts[i2], 1);
        g_list[i2 * CAP + s2] = warp;
        g_gate[i2 * CAP + s2] = g2;
    }
}

// ---------------- Tile scheduler ----------------
__global__ void tile_sched_kernel() {
    if (threadIdx.x == 0) {
        int tot = 0;
        for (int e = 0; e < E_NUM; e++) {
            int nt = (g_counts[e] + 127) >> 7;
            for (int i = 0; i < nt; i++) g_tilemap[tot++] = (e << 16) | i;
        }
        g_ntiles = tot;
    }
}

// ---------------- TF32 tensor-core grouped GEMM ----------------
__device__ __forceinline__ void cp16(unsigned dst, const float* src, bool p) {
    int sz = p ? 16 : 0;
    asm volatile("cp.async.cg.shared.global [%0], [%1], 16, %2;\n"
                 :: "r"(dst), "l"(src), "r"(sz));
}
__device__ __forceinline__ void mma8(float* c, const unsigned* a, const unsigned* b) {
    asm volatile(
        "mma.sync.aligned.m16n8k8.row.col.f32.tf32.tf32.f32 "
        "{%0,%1,%2,%3}, {%4,%5,%6,%7}, {%8,%9}, {%0,%1,%2,%3};\n"
        : "+f"(c[0]), "+f"(c[1]), "+f"(c[2]), "+f"(c[3])
        : "r"(a[0]), "r"(a[1]), "r"(a[2]), "r"(a[3]), "r"(b[0]), "r"(b[1]));
}

#define ST 3          // pipeline stages
#define BK 32         // k per tile
#define AS_LD 36      // As row stride (32 + 4 pad)
#define BS_LD 136     // Bs row stride (128 + 8 pad)
#define A_STAGE (128 * AS_LD)
#define B_STAGE (BK * BS_LD)
#define SMEM_FLOATS (ST * A_STAGE + ST * B_STAGE + 128)

// G1: h = relu(gather(x_t) @ W1[e] + b1[e])  [K=1024, N=4096]
// !G1: atomicAdd(out, gate * (h @ W2[e] + b2[e]))  [K=4096, N=1024]
template<bool G1>
__global__ __launch_bounds__(256, 2)
void moe_gemm(const float* __restrict__ W,
              const float* __restrict__ bias,
              float* __restrict__ final_out)
{
    constexpr int K = G1 ? D_DIM : H_DIM;
    constexpr int N = G1 ? H_DIM : D_DIM;

    if (blockIdx.y >= g_ntiles) return;
    int tm = g_tilemap[blockIdx.y];
    int e = tm >> 16;
    int m0 = (tm & 0xffff) * 128;
    int count = g_counts[e];
    int n0 = blockIdx.x * 128;

    extern __shared__ float smemf[];
    float (*As)[128][AS_LD] = (float (*)[128][AS_LD])smemf;
    float (*Bs)[BK][BS_LD]  = (float (*)[BK][BS_LD])(smemf + ST * A_STAGE);
    int* stok = (int*)(smemf + ST * A_STAGE + ST * B_STAGE);

    int tid = threadIdx.x;
    int wid = tid >> 5, lane = tid & 31;
    int gid = lane >> 2, tig = lane & 3;
    int warp_m = (wid & 1) * 64;
    int warp_n = (wid >> 1) * 32;

    if (tid < 128) {
        int r = m0 + tid;
        stok[tid] = (r < count) ? g_list[e * CAP + r] : -1;
    }
    __syncthreads();

    // loader coords: A: row = tid>>1 (0..127), k-half = (tid&1)*16, 4 float4 each
    //                B: row = tid>>3 (0..31),  n-off  = (tid&7)*16, 4 float4 each
    int a_r  = tid >> 1;
    int a_k0 = (tid & 1) * 16;
    int b_r  = tid >> 3;
    int b_n0 = (tid & 7) * 16;

    const float* We = W + (size_t)e * K * N;
    const float* biasrow = bias + (size_t)e * N;

    const float* arow;
    bool ap;
    if (G1) {
        int t0 = stok[a_r];
        ap = t0 >= 0;
        arow = g_xt + (size_t)(ap ? t0 : 0) * D_DIM;
    } else {
        ap = (m0 + a_r) < count;
        arow = g_hbuf + ((size_t)e * CAP + (ap ? m0 + a_r : 0)) * (size_t)H_DIM;
    }

    unsigned sA[ST], sB[ST];
#pragma unroll
    for (int b = 0; b < ST; b++) {
        sA[b] = (unsigned)__cvta_generic_to_shared(&As[b][a_r][a_k0]);
        sB[b] = (unsigned)__cvta_generic_to_shared(&Bs[b][b_r][b_n0]);
    }

    float acc[4][4][4];
#pragma unroll
    for (int i = 0; i < 4; i++)
#pragma unroll
        for (int j = 0; j < 4; j++)
#pragma unroll
            for (int r = 0; r < 4; r++) acc[i][j][r] = 0.f;

    const int nK = K / BK;

    // prologue: stages 0..ST-2
#pragma unroll
    for (int p = 0; p < ST - 1; ++p) {
        int kk = p * BK;
#pragma unroll
        for (int i = 0; i < 4; i++)
            cp16(sA[p] + i * 16, arow + kk + a_k0 + i * 4, ap);
#pragma unroll
        for (int i = 0; i < 4; i++)
            cp16(sB[p] + i * 16, We + (size_t)(kk + b_r) * N + n0 + b_n0 + i * 4, true);
        asm volatile("cp.async.commit_group;\n");
    }

    for (int t = 0; t < nK; ++t) {
        asm volatile("cp.async.wait_group %0;\n" :: "n"(ST - 2));
        __syncthreads();

        int nt_ = t + ST - 1;
        if (nt_ < nK) {
            int kk = nt_ * BK;
            int b = nt_ % ST;
#pragma unroll
            for (int i = 0; i < 4; i++)
                cp16(sA[b] + i * 16, arow + kk + a_k0 + i * 4, ap);
#pragma unroll
            for (int i = 0; i < 4; i++)
                cp16(sB[b] + i * 16, We + (size_t)(kk + b_r) * N + n0 + b_n0 + i * 4, true);
            asm volatile("cp.async.commit_group;\n");
        }

        int buf = t % ST;
#pragma unroll
        for (int ks = 0; ks < BK; ks += 8) {
            unsigned af[4][4], bf[4][2];
#pragma unroll
            for (int mt = 0; mt < 4; mt++) {
                int m = warp_m + mt * 16 + gid;
                af[mt][0] = __float_as_uint(As[buf][m][ks + tig]);
                af[mt][1] = __float_as_uint(As[buf][m + 8][ks + tig]);
                af[mt][2] = __float_as_uint(As[buf][m][ks + tig + 4]);
                af[mt][3] = __float_as_uint(As[buf][m + 8][ks + tig + 4]);
            }
#pragma unroll
            for (int nt2 = 0; nt2 < 4; nt2++) {
                int n = warp_n + nt2 * 8 + gid;
                bf[nt2][0] = cvt_tf32(Bs[buf][ks + tig][n]);
                bf[nt2][1] = cvt_tf32(Bs[buf][ks + tig + 4][n]);
            }
#pragma unroll
            for (int mt = 0; mt < 4; mt++)
#pragma unroll
                for (int nt2 = 0; nt2 < 4; nt2++)
                    mma8(acc[mt][nt2], af[mt], bf[nt2]);
        }
    }

    // ---------------- epilogue ----------------
#pragma unroll
    for (int mt = 0; mt < 4; mt++) {
        int mg0 = m0 + warp_m + mt * 16 + gid;
#pragma unroll
        for (int half = 0; half < 2; half++) {
            int mg = half ? (mg0 + 8) : mg0;
            if (mg >= count) continue;
            if (G1) {
                size_t rowoff = ((size_t)e * CAP + mg) * (size_t)N;
#pragma unroll
                for (int nt2 = 0; nt2 < 4; nt2++) {
                    int n = n0 + warp_n + nt2 * 8 + tig * 2;
                    float v0 = acc[mt][nt2][half * 2 + 0] + biasrow[n];
                    float v1 = acc[mt][nt2][half * 2 + 1] + biasrow[n + 1];
                    v0 = __uint_as_float(cvt_tf32(fmaxf(v0, 0.f)));
                    v1 = __uint_as_float(cvt_tf32(fmaxf(v1, 0.f)));
                    *(float2*)(g_hbuf + rowoff + n) = make_float2(v0, v1);
                }
            } else {
                float gate = g_gate[e * CAP + mg];
                int tok = stok[mg - m0];
                float* orow = final_out + (size_t)tok * D_DIM;
#pragma unroll
                for (int nt2 = 0; nt2 < 4; nt2++) {
                    int n = n0 + warp_n + nt2 * 8 + tig * 2;
                    float v0 = gate * (acc[mt][nt2][half * 2 + 0] + biasrow[n]);
                    float v1 = gate * (acc[mt][nt2][half * 2 + 1] + biasrow[n + 1]);
                    atomicAdd(orow + n, v0);
                    atomicAdd(orow + n + 1, v1);
                }
            }
        }
    }
}

extern "C" void kernel_launch(void* const* d_in, const int* in_sizes, int n_in,
                              void* d_out, int out_size) {
    const float* x     = (const float*)d_in[0];
    const float* noise = (const float*)d_in[1];
    const float* Wr    = (const float*)d_in[2];
    const float* br    = (const float*)d_in[3];
    const float* Wn    = (const float*)d_in[4];
    const float* bn    = (const float*)d_in[5];
    const float* W1    = (const float*)d_in[6];
    const float* b1    = (const float*)d_in[7];
    const float* W2    = (const float*)d_in[8];
    const float* b2    = (const float*)d_in[9];
    float* out = (float*)d_out;

    float* final_out  = out;                               // [B,S,D]
    float* gating_out = out + (size_t)T_TOK * D_DIM;       // [B,S,E]

    static bool attr_set = false;
    if (!attr_set) {
        cudaFuncSetAttribute(moe_gemm<true>,  cudaFuncAttributeMaxDynamicSharedMemorySize,
                             SMEM_FLOATS * 4);
        cudaFuncSetAttribute(moe_gemm<false>, cudaFuncAttributeMaxDynamicSharedMemorySize,
                             SMEM_FLOATS * 4);
        attr_set = true;
    }

    zero_counts_kernel<<<1, 32>>>();
    zero_out_kernel<<<T_TOK, 256>>>(final_out);
    router_kernel<<<512, 256>>>(x, noise, Wr, br, Wn, bn, gating_out);
    tile_sched_kernel<<<1, 32>>>();

    {
        dim3 grid(H_DIM / 128, MAXTILE);
        moe_gemm<true><<<grid, 256, SMEM_FLOATS * 4>>>(W1, b1, nullptr);
    }
    {
        dim3 grid(D_DIM / 128, MAXTILE);
        moe_gemm<false><<<grid, 256, SMEM_FLOATS * 4>>>(W2, b2, final_out);
    }
}

// round 13
// speedup vs baseline: 1.2265x; 1.2265x over previous
#include <cuda_runtime.h>
#include <math.h>

#define T_TOK 4096   // B*S
#define D_DIM 1024
#define E_NUM 8
#define H_DIM 4096
#define CAP   4096
#define MAXTILE 72

// ---- static scratch ----
__device__ float g_hbuf[(size_t)E_NUM * CAP * H_DIM];   // tf32-rounded h
__device__ float g_ybuf[(size_t)E_NUM * CAP * D_DIM];
__device__ float g_xt[(size_t)T_TOK * D_DIM];           // tf32-rounded x
__device__ float g_w1t[(size_t)E_NUM * D_DIM * H_DIM];  // tf32-rounded W1
__device__ float g_w2t[(size_t)E_NUM * H_DIM * D_DIM];  // tf32-rounded W2
__device__ int   g_counts[E_NUM];
__device__ int   g_list[E_NUM * CAP];
__device__ float g_gate[E_NUM * CAP];
__device__ int   g_pair[T_TOK * 2];
__device__ int   g_tilemap[MAXTILE];
__device__ int   g_ntiles;

__global__ void zero_counts_kernel() {
    if (threadIdx.x < E_NUM) g_counts[threadIdx.x] = 0;
}

__device__ __forceinline__ unsigned cvt_tf32(float f) {
    unsigned o;
    asm volatile("cvt.rna.tf32.f32 %0, %1;\n" : "=r"(o) : "f"(f));
    return o;
}

// ---- pre-convert W1 and W2 to tf32 (same cvt.rna the mainloop used) ----
#define W_ELEMS ((size_t)E_NUM * D_DIM * H_DIM)   // per weight tensor
__global__ void wconv_kernel(const float* __restrict__ W1,
                             const float* __restrict__ W2) {
    size_t i = (size_t)blockIdx.x * blockDim.x + threadIdx.x;   // float4 idx
    size_t q = W_ELEMS / 4;
    const float4* src;
    float4* dst;
    if (i < q) { src = (const float4*)W1; dst = (float4*)g_w1t; }
    else       { src = (const float4*)W2; dst = (float4*)g_w2t; i -= q; }
    float4 v = src[i];
    v.x = __uint_as_float(cvt_tf32(v.x));
    v.y = __uint_as_float(cvt_tf32(v.y));
    v.z = __uint_as_float(cvt_tf32(v.z));
    v.w = __uint_as_float(cvt_tf32(v.w));
    dst[i] = v;
}

// ---------------- Router: one warp per token ----------------
// fp32 fast path; fp64 re-check only when the top2/top3 margin is tiny.
__global__ void router_kernel(const float* __restrict__ x,
                              const float* __restrict__ noise,
                              const float* __restrict__ Wr, const float* __restrict__ br,
                              const float* __restrict__ Wn, const float* __restrict__ bn,
                              float* __restrict__ gate_out /* [T,E] */) {
    int warp = (blockIdx.x * blockDim.x + threadIdx.x) >> 5;
    int lane = threadIdx.x & 31;
    if (warp >= T_TOK) return;

    const float* xr = x + (size_t)warp * D_DIM;
    float* xtr = g_xt + (size_t)warp * D_DIM;
    float aR[8], aN[8];
#pragma unroll
    for (int e = 0; e < 8; e++) { aR[e] = 0.f; aN[e] = 0.f; }

    for (int d0 = lane * 4; d0 < D_DIM; d0 += 32 * 4) {
        float4 xv = *(const float4*)(xr + d0);
        float4 xt;
        xt.x = __uint_as_float(cvt_tf32(xv.x));
        xt.y = __uint_as_float(cvt_tf32(xv.y));
        xt.z = __uint_as_float(cvt_tf32(xv.z));
        xt.w = __uint_as_float(cvt_tf32(xv.w));
        *(float4*)(xtr + d0) = xt;
        float xs[4] = {xv.x, xv.y, xv.z, xv.w};
#pragma unroll
        for (int u = 0; u < 4; ++u) {
            float xd = xs[u];
            const float4* wr = (const float4*)(Wr + (size_t)(d0 + u) * E_NUM);
            float4 r0 = wr[0], r1 = wr[1];
            const float4* wn = (const float4*)(Wn + (size_t)(d0 + u) * E_NUM);
            float4 q0 = wn[0], q1 = wn[1];
            aR[0] += xd * r0.x; aR[1] += xd * r0.y; aR[2] += xd * r0.z; aR[3] += xd * r0.w;
            aR[4] += xd * r1.x; aR[5] += xd * r1.y; aR[6] += xd * r1.z; aR[7] += xd * r1.w;
            aN[0] += xd * q0.x; aN[1] += xd * q0.y; aN[2] += xd * q0.z; aN[3] += xd * q0.w;
            aN[4] += xd * q1.x; aN[5] += xd * q1.y; aN[6] += xd * q1.z; aN[7] += xd * q1.w;
        }
    }
#pragma unroll
    for (int off = 16; off > 0; off >>= 1) {
#pragma unroll
        for (int e = 0; e < 8; e++) {
            aR[e] += __shfl_xor_sync(0xffffffffu, aR[e], off);
            aN[e] += __shfl_xor_sync(0xffffffffu, aN[e], off);
        }
    }

    if (lane == 0) {
        float lg[8], noisy[8];
#pragma unroll
        for (int e = 0; e < 8; e++) {
            lg[e] = aR[e] + br[e];
            float nl = aN[e] + bn[e];
            float sp = (nl > 20.f) ? nl : log1pf(expf(nl));
            noisy[e] = lg[e] + noise[(size_t)warp * E_NUM + e] * sp;
        }
        int i1 = 0;
#pragma unroll
        for (int e = 1; e < 8; e++) if (noisy[e] > noisy[i1]) i1 = e;
        int i2 = -1;
#pragma unroll
        for (int e = 0; e < 8; e++) {
            if (e == i1) continue;
            if (i2 < 0 || noisy[e] > noisy[i2]) i2 = e;
        }
        int i3 = -1;
#pragma unroll
        for (int e = 0; e < 8; e++) {
            if (e == i1 || e == i2) continue;
            if (i3 < 0 || noisy[e] > noisy[i3]) i3 = e;
        }
        float gap = noisy[i2] - noisy[i3];
        float d12 = noisy[i1] - noisy[i2];
        if (gap < 1e-3f) {
            double nd[8];
#pragma unroll
            for (int e = 0; e < 8; e++) {
                double nl = (double)aN[e] + (double)bn[e];
                double sp = log1p(exp(nl));
                nd[e] = (double)lg[e] + (double)noise[(size_t)warp * E_NUM + e] * sp;
            }
            i1 = 0;
#pragma unroll
            for (int e = 1; e < 8; e++) if (nd[e] > nd[i1]) i1 = e;
            i2 = -1;
#pragma unroll
            for (int e = 0; e < 8; e++) {
                if (e == i1) continue;
                if (i2 < 0 || nd[e] > nd[i2]) i2 = e;
            }
            d12 = (float)(nd[i1] - nd[i2]);
        }
        float e2 = expf(-d12);
        float s = 1.0f + e2;
        float g1 = 1.0f / s, g2 = e2 / s;

        float lm = lg[0];
#pragma unroll
        for (int e = 1; e < 8; e++) lm = fmaxf(lm, lg[e]);
        float se = 0.f, ex[8];
#pragma unroll
        for (int e = 0; e < 8; e++) { ex[e] = expf(lg[e] - lm); se += ex[e]; }
#pragma unroll
        for (int e = 0; e < 8; e++)
            gate_out[(size_t)warp * E_NUM + e] = ex[e] / se;

        int s1 = atomicAdd(&g_counts[i1], 1);
        g_list[i1 * CAP + s1] = warp;
        g_gate[i1 * CAP + s1] = g1;
        int s2 = atomicAdd(&g_counts[i2], 1);
        g_list[i2 * CAP + s2] = warp;
        g_gate[i2 * CAP + s2] = g2;
        g_pair[warp * 2 + 0] = i1 * CAP + s1;
        g_pair[warp * 2 + 1] = i2 * CAP + s2;
    }
}

// ---------------- Tile scheduler ----------------
__global__ void tile_sched_kernel() {
    if (threadIdx.x == 0) {
        int tot = 0;
        for (int e = 0; e < E_NUM; e++) {
            int nt = (g_counts[e] + 127) >> 7;
            for (int i = 0; i < nt; i++) g_tilemap[tot++] = (e << 16) | i;
        }
        g_ntiles = tot;
    }
}

// ---------------- TF32 tensor-core grouped GEMM ----------------
__device__ __forceinline__ void cp16(unsigned dst, const float* src, bool p) {
    int sz = p ? 16 : 0;
    asm volatile("cp.async.cg.shared.global [%0], [%1], 16, %2;\n"
                 :: "r"(dst), "l"(src), "r"(sz));
}
__device__ __forceinline__ void mma8(float* c, const unsigned* a, const unsigned* b) {
    asm volatile(
        "mma.sync.aligned.m16n8k8.row.col.f32.tf32.tf32.f32 "
        "{%0,%1,%2,%3}, {%4,%5,%6,%7}, {%8,%9}, {%0,%1,%2,%3};\n"
        : "+f"(c[0]), "+f"(c[1]), "+f"(c[2]), "+f"(c[3])
        : "r"(a[0]), "r"(a[1]), "r"(a[2]), "r"(a[3]), "r"(b[0]), "r"(b[1]));
}

#define ST 3   // pipeline stages

// G1: h = relu(gather(x_t) @ g_w1t[e] + b1[e])  [K=1024, N=4096]
// !G1: y = gate * (h @ g_w2t[e] + b2[e])        [K=4096, N=1024]
// NOTE: weights referenced via device symbols INSIDE the kernel (host cannot
// pass __device__ symbol addresses as arguments — R11 bug).
template<bool G1>
__global__ __launch_bounds__(256, 2)
void moe_gemm(const float* __restrict__ bias)
{
    constexpr int K = G1 ? D_DIM : H_DIM;
    constexpr int N = G1 ? H_DIM : D_DIM;

    if (blockIdx.y >= g_ntiles) return;
    int tm = g_tilemap[blockIdx.y];
    int e = tm >> 16;
    int m0 = (tm & 0xffff) * 128;
    int count = g_counts[e];
    int n0 = blockIdx.x * 128;

    __shared__ float As[ST][128][20];
    __shared__ float Bs[ST][16][136];
    __shared__ int stok[128];

    int tid = threadIdx.x;
    int wid = tid >> 5, lane = tid & 31;
    int gid = lane >> 2, tig = lane & 3;
    int warp_m = (wid & 1) * 64;
    int warp_n = (wid >> 1) * 32;

    if (G1) {
        if (tid < 128) {
            int r = m0 + tid;
            stok[tid] = (r < count) ? g_list[e * CAP + r] : -1;
        }
        __syncthreads();
    }

    int a_m  = tid >> 2;           // 0..63 (and +64)
    int a_kq = (tid & 3) * 4;      // 0,4,8,12
    int b_r  = tid >> 4;           // 0..15
    int b_c  = (tid & 15) * 4;     // 0..60 (and +64)

    const float* Wbase = G1 ? g_w1t : g_w2t;
    const float* We = Wbase + (size_t)e * K * N;
    const float* biasrow = bias + (size_t)e * N;

    const float *arow0, *arow1;
    bool ap0, ap1;
    if (G1) {
        int t0 = stok[a_m], t1 = stok[a_m + 64];
        ap0 = t0 >= 0; ap1 = t1 >= 0;
        arow0 = g_xt + (size_t)(ap0 ? t0 : 0) * D_DIM;
        arow1 = g_xt + (size_t)(ap1 ? t1 : 0) * D_DIM;
    } else {
        ap0 = (m0 + a_m) < count;
        ap1 = (m0 + a_m + 64) < count;
        arow0 = g_hbuf + ((size_t)e * CAP + (ap0 ? m0 + a_m : 0)) * (size_t)H_DIM;
        arow1 = g_hbuf + ((size_t)e * CAP + (ap1 ? m0 + a_m + 64 : 0)) * (size_t)H_DIM;
    }

    unsigned sA0[ST], sA1[ST], sB0[ST], sB1[ST];
#pragma unroll
    for (int b = 0; b < ST; b++) {
        sA0[b] = (unsigned)__cvta_generic_to_shared(&As[b][a_m][a_kq]);
        sA1[b] = (unsigned)__cvta_generic_to_shared(&As[b][a_m + 64][a_kq]);
        sB0[b] = (unsigned)__cvta_generic_to_shared(&Bs[b][b_r][b_c]);
        sB1[b] = (unsigned)__cvta_generic_to_shared(&Bs[b][b_r][b_c + 64]);
    }

    float acc[4][4][4];
#pragma unroll
    for (int i = 0; i < 4; i++)
#pragma unroll
        for (int j = 0; j < 4; j++)
#pragma unroll
            for (int r = 0; r < 4; r++) acc[i][j][r] = 0.f;

    const int nK = K / 16;

#pragma unroll
    for (int p = 0; p < ST - 1; ++p) {
        int kk = p * 16;
        cp16(sA0[p], arow0 + kk + a_kq, ap0);
        cp16(sA1[p], arow1 + kk + a_kq, ap1);
        cp16(sB0[p], We + (size_t)(kk + b_r) * N + n0 + b_c, true);
        cp16(sB1[p], We + (size_t)(kk + b_r) * N + n0 + b_c + 64, true);
        asm volatile("cp.async.commit_group;\n");
    }

    for (int t = 0; t < nK; ++t) {
        asm volatile("cp.async.wait_group %0;\n" :: "n"(ST - 2));
        __syncthreads();

        int nt_ = t + ST - 1;
        if (nt_ < nK) {
            int kk = nt_ * 16;
            int b = nt_ % ST;
            cp16(sA0[b], arow0 + kk + a_kq, ap0);
            cp16(sA1[b], arow1 + kk + a_kq, ap1);
            cp16(sB0[b], We + (size_t)(kk + b_r) * N + n0 + b_c, true);
            cp16(sB1[b], We + (size_t)(kk + b_r) * N + n0 + b_c + 64, true);
            asm volatile("cp.async.commit_group;\n");
        }

        int buf = t % ST;
#pragma unroll
        for (int ks = 0; ks < 16; ks += 8) {
            unsigned af[4][4], bf[4][2];
#pragma unroll
            for (int mt = 0; mt < 4; mt++) {
                int m = warp_m + mt * 16 + gid;
                af[mt][0] = __float_as_uint(As[buf][m][ks + tig]);
                af[mt][1] = __float_as_uint(As[buf][m + 8][ks + tig]);
                af[mt][2] = __float_as_uint(As[buf][m][ks + tig + 4]);
                af[mt][3] = __float_as_uint(As[buf][m + 8][ks + tig + 4]);
            }
#pragma unroll
            for (int nt2 = 0; nt2 < 4; nt2++) {
                int n = warp_n + nt2 * 8 + gid;
                bf[nt2][0] = __float_as_uint(Bs[buf][ks + tig][n]);
                bf[nt2][1] = __float_as_uint(Bs[buf][ks + tig + 4][n]);
            }
#pragma unroll
            for (int mt = 0; mt < 4; mt++)
#pragma unroll
                for (int nt2 = 0; nt2 < 4; nt2++)
                    mma8(acc[mt][nt2], af[mt], bf[nt2]);
        }
    }

    // ---------------- epilogue ----------------
    float* outbuf = G1 ? g_hbuf : g_ybuf;
#pragma unroll
    for (int mt = 0; mt < 4; mt++) {
        int mg0 = m0 + warp_m + mt * 16 + gid;
#pragma unroll
        for (int half = 0; half < 2; half++) {
            int mg = half ? (mg0 + 8) : mg0;
            if (mg >= count) continue;
            size_t rowoff = ((size_t)e * CAP + mg) * (size_t)N;
            float gate = 1.0f;
            if (!G1) gate = g_gate[e * CAP + mg];
#pragma unroll
            for (int nt2 = 0; nt2 < 4; nt2++) {
                int n = n0 + warp_n + nt2 * 8 + tig * 2;
                float v0 = acc[mt][nt2][half * 2 + 0] + biasrow[n];
                float v1 = acc[mt][nt2][half * 2 + 1] + biasrow[n + 1];
                if (G1) {
                    v0 = __uint_as_float(cvt_tf32(fmaxf(v0, 0.f)));
                    v1 = __uint_as_float(cvt_tf32(fmaxf(v1, 0.f)));
                } else {
                    v0 *= gate;
                    v1 *= gate;
                }
                *(float2*)(outbuf + rowoff + n) = make_float2(v0, v1);
            }
        }
    }
}

// ---------------- Combine: out[t] = y[pair0] + y[pair1] ----------------
__global__ void combine_kernel(float* __restrict__ out) {
    int t = blockIdx.x;
    int i = threadIdx.x;
    int p0 = g_pair[2 * t + 0];
    int p1 = g_pair[2 * t + 1];
    float4 a = ((const float4*)(g_ybuf + (size_t)p0 * D_DIM))[i];
    float4 b = ((const float4*)(g_ybuf + (size_t)p1 * D_DIM))[i];
    float4 r;
    r.x = a.x + b.x; r.y = a.y + b.y; r.z = a.z + b.z; r.w = a.w + b.w;
    ((float4*)(out + (size_t)t * D_DIM))[i] = r;
}

extern "C" void kernel_launch(void* const* d_in, const int* in_sizes, int n_in,
                              void* d_out, int out_size) {
    const float* x     = (const float*)d_in[0];
    const float* noise = (const float*)d_in[1];
    const float* Wr    = (const float*)d_in[2];
    const float* br    = (const float*)d_in[3];
    const float* Wn    = (const float*)d_in[4];
    const float* bn    = (const float*)d_in[5];
    const float* W1    = (const float*)d_in[6];
    const float* b1    = (const float*)d_in[7];
    const float* W2    = (const float*)d_in[8];
    const float* b2    = (const float*)d_in[9];
    float* out = (float*)d_out;

    float* final_out  = out;                               // [B,S,D]
    float* gating_out = out + (size_t)T_TOK * D_DIM;       // [B,S,E]

    zero_counts_kernel<<<1, 32>>>();
    wconv_kernel<<<(unsigned)(2 * (W_ELEMS / 4) / 256), 256>>>(W1, W2);
    router_kernel<<<512, 256>>>(x, noise, Wr, br, Wn, bn, gating_out);
    tile_sched_kernel<<<1, 32>>>();

    {
        dim3 grid(H_DIM / 128, MAXTILE);
        moe_gemm<true><<<grid, 256>>>(b1);
    }
    {
        dim3 grid(D_DIM / 128, MAXTILE);
        moe_gemm<false><<<grid, 256>>>(b2);
    }
    combine_kernel<<<T_TOK, 256>>>(final_out);
}

// round 15
// speedup vs baseline: 1.3140x; 1.0714x over previous
#include <cuda_runtime.h>
#include <math.h>

#define T_TOK 4096   // B*S
#define D_DIM 1024
#define E_NUM 8
#define H_DIM 4096
#define CAP   4096
#define MAXTILE 72

// ---- static scratch ----
__device__ float g_hbuf[(size_t)E_NUM * CAP * H_DIM];   // tf32-rounded h
__device__ float g_ybuf[(size_t)E_NUM * CAP * D_DIM];
__device__ float g_xt[(size_t)T_TOK * D_DIM];           // tf32-rounded x
__device__ int   g_counts[E_NUM];
__device__ int   g_list[E_NUM * CAP];
__device__ float g_gate[E_NUM * CAP];
__device__ int   g_pair[T_TOK * 2];
__device__ int   g_tilemap[MAXTILE];
__device__ int   g_ntiles;

__global__ void zero_counts_kernel() {
    if (threadIdx.x < E_NUM) g_counts[threadIdx.x] = 0;
}

__device__ __forceinline__ unsigned cvt_tf32(float f) {
    unsigned o;
    asm volatile("cvt.rna.tf32.f32 %0, %1;\n" : "=r"(o) : "f"(f));
    return o;
}

// ---------------- Router: one warp per token ----------------
// fp32 fast path; fp64 re-check only when the top2/top3 margin is tiny.
// (harness-proven in R9/R13 including post-timing determinism check)
__global__ void router_kernel(const float* __restrict__ x,
                              const float* __restrict__ noise,
                              const float* __restrict__ Wr, const float* __restrict__ br,
                              const float* __restrict__ Wn, const float* __restrict__ bn,
                              float* __restrict__ gate_out /* [T,E] */) {
    int warp = (blockIdx.x * blockDim.x + threadIdx.x) >> 5;
    int lane = threadIdx.x & 31;
    if (warp >= T_TOK) return;

    const float* xr = x + (size_t)warp * D_DIM;
    float* xtr = g_xt + (size_t)warp * D_DIM;
    float aR[8], aN[8];
#pragma unroll
    for (int e = 0; e < 8; e++) { aR[e] = 0.f; aN[e] = 0.f; }

    for (int d0 = lane * 4; d0 < D_DIM; d0 += 32 * 4) {
        float4 xv = *(const float4*)(xr + d0);
        float4 xt;
        xt.x = __uint_as_float(cvt_tf32(xv.x));
        xt.y = __uint_as_float(cvt_tf32(xv.y));
        xt.z = __uint_as_float(cvt_tf32(xv.z));
        xt.w = __uint_as_float(cvt_tf32(xv.w));
        *(float4*)(xtr + d0) = xt;
        float xs[4] = {xv.x, xv.y, xv.z, xv.w};
#pragma unroll
        for (int u = 0; u < 4; ++u) {
            float xd = xs[u];
            const float4* wr = (const float4*)(Wr + (size_t)(d0 + u) * E_NUM);
            float4 r0 = wr[0], r1 = wr[1];
            const float4* wn = (const float4*)(Wn + (size_t)(d0 + u) * E_NUM);
            float4 q0 = wn[0], q1 = wn[1];
            aR[0] += xd * r0.x; aR[1] += xd * r0.y; aR[2] += xd * r0.z; aR[3] += xd * r0.w;
            aR[4] += xd * r1.x; aR[5] += xd * r1.y; aR[6] += xd * r1.z; aR[7] += xd * r1.w;
            aN[0] += xd * q0.x; aN[1] += xd * q0.y; aN[2] += xd * q0.z; aN[3] += xd * q0.w;
            aN[4] += xd * q1.x; aN[5] += xd * q1.y; aN[6] += xd * q1.z; aN[7] += xd * q1.w;
        }
    }
#pragma unroll
    for (int off = 16; off > 0; off >>= 1) {
#pragma unroll
        for (int e = 0; e < 8; e++) {
            aR[e] += __shfl_xor_sync(0xffffffffu, aR[e], off);
            aN[e] += __shfl_xor_sync(0xffffffffu, aN[e], off);
        }
    }

    if (lane == 0) {
        float lg[8], noisy[8];
#pragma unroll
        for (int e = 0; e < 8; e++) {
            lg[e] = aR[e] + br[e];
            float nl = aN[e] + bn[e];
            float sp = (nl > 20.f) ? nl : log1pf(expf(nl));
            noisy[e] = lg[e] + noise[(size_t)warp * E_NUM + e] * sp;
        }
        int i1 = 0;
#pragma unroll
        for (int e = 1; e < 8; e++) if (noisy[e] > noisy[i1]) i1 = e;
        int i2 = -1;
#pragma unroll
        for (int e = 0; e < 8; e++) {
            if (e == i1) continue;
            if (i2 < 0 || noisy[e] > noisy[i2]) i2 = e;
        }
        int i3 = -1;
#pragma unroll
        for (int e = 0; e < 8; e++) {
            if (e == i1 || e == i2) continue;
            if (i3 < 0 || noisy[e] > noisy[i3]) i3 = e;
        }
        float gap = noisy[i2] - noisy[i3];
        float d12 = noisy[i1] - noisy[i2];
        if (gap < 1e-3f) {
            double nd[8];
#pragma unroll
            for (int e = 0; e < 8; e++) {
                double nl = (double)aN[e] + (double)bn[e];
                double sp = log1p(exp(nl));
                nd[e] = (double)lg[e] + (double)noise[(size_t)warp * E_NUM + e] * sp;
            }
            i1 = 0;
#pragma unroll
            for (int e = 1; e < 8; e++) if (nd[e] > nd[i1]) i1 = e;
            i2 = -1;
#pragma unroll
            for (int e = 0; e < 8; e++) {
                if (e == i1) continue;
                if (i2 < 0 || nd[e] > nd[i2]) i2 = e;
            }
            d12 = (float)(nd[i1] - nd[i2]);
        }
        float e2 = expf(-d12);
        float s = 1.0f + e2;
        float g1 = 1.0f / s, g2 = e2 / s;

        float lm = lg[0];
#pragma unroll
        for (int e = 1; e < 8; e++) lm = fmaxf(lm, lg[e]);
        float se = 0.f, ex[8];
#pragma unroll
        for (int e = 0; e < 8; e++) { ex[e] = expf(lg[e] - lm); se += ex[e]; }
#pragma unroll
        for (int e = 0; e < 8; e++)
            gate_out[(size_t)warp * E_NUM + e] = ex[e] / se;

        int s1 = atomicAdd(&g_counts[i1], 1);
        g_list[i1 * CAP + s1] = warp;
        g_gate[i1 * CAP + s1] = g1;
        int s2 = atomicAdd(&g_counts[i2], 1);
        g_list[i2 * CAP + s2] = warp;
        g_gate[i2 * CAP + s2] = g2;
        g_pair[warp * 2 + 0] = i1 * CAP + s1;
        g_pair[warp * 2 + 1] = i2 * CAP + s2;
    }
}

// ---------------- Tile scheduler ----------------
__global__ void tile_sched_kernel() {
    if (threadIdx.x == 0) {
        int tot = 0;
        for (int e = 0; e < E_NUM; e++) {
            int nt = (g_counts[e] + 127) >> 7;
            for (int i = 0; i < nt; i++) g_tilemap[tot++] = (e << 16) | i;
        }
        g_ntiles = tot;
    }
}

// ---------------- TF32 tensor-core grouped GEMM (R6-verbatim body) ----------------
__device__ __forceinline__ void cp16(unsigned dst, const float* src, bool p) {
    int sz = p ? 16 : 0;
    asm volatile("cp.async.cg.shared.global [%0], [%1], 16, %2;\n"
                 :: "r"(dst), "l"(src), "r"(sz));
}
__device__ __forceinline__ void mma8(float* c, const unsigned* a, const unsigned* b) {
    asm volatile(
        "mma.sync.aligned.m16n8k8.row.col.f32.tf32.tf32.f32 "
        "{%0,%1,%2,%3}, {%4,%5,%6,%7}, {%8,%9}, {%0,%1,%2,%3};\n"
        : "+f"(c[0]), "+f"(c[1]), "+f"(c[2]), "+f"(c[3])
        : "r"(a[0]), "r"(a[1]), "r"(a[2]), "r"(a[3]), "r"(b[0]), "r"(b[1]));
}

#define ST 3   // pipeline stages

// G1: h = relu(gather(x_t) @ W1[e] + b1[e])  [K=1024, N=4096]
// !G1: y = gate * (h @ W2[e] + b2[e])        [K=4096, N=1024]
template<bool G1>
__global__ __launch_bounds__(256, 2)
void moe_gemm(const float* __restrict__ W,
              const float* __restrict__ bias)
{
    constexpr int K = G1 ? D_DIM : H_DIM;
    constexpr int N = G1 ? H_DIM : D_DIM;

    if (blockIdx.y >= g_ntiles) return;
    int tm = g_tilemap[blockIdx.y];
    int e = tm >> 16;
    int m0 = (tm & 0xffff) * 128;
    int count = g_counts[e];
    int n0 = blockIdx.x * 128;

    __shared__ float As[ST][128][20];
    __shared__ float Bs[ST][16][136];
    __shared__ int stok[128];

    int tid = threadIdx.x;
    int wid = tid >> 5, lane = tid & 31;
    int gid = lane >> 2, tig = lane & 3;
    int warp_m = (wid & 1) * 64;
    int warp_n = (wid >> 1) * 32;

    if (G1) {
        if (tid < 128) {
            int r = m0 + tid;
            stok[tid] = (r < count) ? g_list[e * CAP + r] : -1;
        }
        __syncthreads();
    }

    int a_m  = tid >> 2;           // 0..63 (and +64)
    int a_kq = (tid & 3) * 4;      // 0,4,8,12
    int b_r  = tid >> 4;           // 0..15
    int b_c  = (tid & 15) * 4;     // 0..60 (and +64)

    const float* We = W + (size_t)e * K * N;
    const float* biasrow = bias + (size_t)e * N;

    const float *arow0, *arow1;
    bool ap0, ap1;
    if (G1) {
        int t0 = stok[a_m], t1 = stok[a_m + 64];
        ap0 = t0 >= 0; ap1 = t1 >= 0;
        arow0 = g_xt + (size_t)(ap0 ? t0 : 0) * D_DIM;
        arow1 = g_xt + (size_t)(ap1 ? t1 : 0) * D_DIM;
    } else {
        ap0 = (m0 + a_m) < count;
        ap1 = (m0 + a_m + 64) < count;
        arow0 = g_hbuf + ((size_t)e * CAP + (ap0 ? m0 + a_m : 0)) * (size_t)H_DIM;
        arow1 = g_hbuf + ((size_t)e * CAP + (ap1 ? m0 + a_m + 64 : 0)) * (size_t)H_DIM;
    }

    unsigned sA0[ST], sA1[ST], sB0[ST], sB1[ST];
#pragma unroll
    for (int b = 0; b < ST; b++) {
        sA0[b] = (unsigned)__cvta_generic_to_shared(&As[b][a_m][a_kq]);
        sA1[b] = (unsigned)__cvta_generic_to_shared(&As[b][a_m + 64][a_kq]);
        sB0[b] = (unsigned)__cvta_generic_to_shared(&Bs[b][b_r][b_c]);
        sB1[b] = (unsigned)__cvta_generic_to_shared(&Bs[b][b_r][b_c + 64]);
    }

    float acc[4][4][4];
#pragma unroll
    for (int i = 0; i < 4; i++)
#pragma unroll
        for (int j = 0; j < 4; j++)
#pragma unroll
            for (int r = 0; r < 4; r++) acc[i][j][r] = 0.f;

    const int nK = K / 16;

#pragma unroll
    for (int p = 0; p < ST - 1; ++p) {
        int kk = p * 16;
        cp16(sA0[p], arow0 + kk + a_kq, ap0);
        cp16(sA1[p], arow1 + kk + a_kq, ap1);
        cp16(sB0[p], We + (size_t)(kk + b_r) * N + n0 + b_c, true);
        cp16(sB1[p], We + (size_t)(kk + b_r) * N + n0 + b_c + 64, true);
        asm volatile("cp.async.commit_group;\n");
    }

    for (int t = 0; t < nK; ++t) {
        asm volatile("cp.async.wait_group %0;\n" :: "n"(ST - 2));
        __syncthreads();

        int nt_ = t + ST - 1;
        if (nt_ < nK) {
            int kk = nt_ * 16;
            int b = nt_ % ST;
            cp16(sA0[b], arow0 + kk + a_kq, ap0);
            cp16(sA1[b], arow1 + kk + a_kq, ap1);
            cp16(sB0[b], We + (size_t)(kk + b_r) * N + n0 + b_c, true);
            cp16(sB1[b], We + (size_t)(kk + b_r) * N + n0 + b_c + 64, true);
            asm volatile("cp.async.commit_group;\n");
        }

        int buf = t % ST;
#pragma unroll
        for (int ks = 0; ks < 16; ks += 8) {
            unsigned af[4][4], bf[4][2];
#pragma unroll
            for (int mt = 0; mt < 4; mt++) {
                int m = warp_m + mt * 16 + gid;
                af[mt][0] = __float_as_uint(As[buf][m][ks + tig]);
                af[mt][1] = __float_as_uint(As[buf][m + 8][ks + tig]);
                af[mt][2] = __float_as_uint(As[buf][m][ks + tig + 4]);
                af[mt][3] = __float_as_uint(As[buf][m + 8][ks + tig + 4]);
            }
#pragma unroll
            for (int nt2 = 0; nt2 < 4; nt2++) {
                int n = warp_n + nt2 * 8 + gid;
                bf[nt2][0] = cvt_tf32(Bs[buf][ks + tig][n]);
                bf[nt2][1] = cvt_tf32(Bs[buf][ks + tig + 4][n]);
            }
#pragma unroll
            for (int mt = 0; mt < 4; mt++)
#pragma unroll
                for (int nt2 = 0; nt2 < 4; nt2++)
                    mma8(acc[mt][nt2], af[mt], bf[nt2]);
        }
    }

    // ---------------- epilogue ----------------
    float* outbuf = G1 ? g_hbuf : g_ybuf;
#pragma unroll
    for (int mt = 0; mt < 4; mt++) {
        int mg0 = m0 + warp_m + mt * 16 + gid;
#pragma unroll
        for (int half = 0; half < 2; half++) {
            int mg = half ? (mg0 + 8) : mg0;
            if (mg >= count) continue;
            size_t rowoff = ((size_t)e * CAP + mg) * (size_t)N;
            float gate = 1.0f;
            if (!G1) gate = g_gate[e * CAP + mg];
#pragma unroll
            for (int nt2 = 0; nt2 < 4; nt2++) {
                int n = n0 + warp_n + nt2 * 8 + tig * 2;
                float v0 = acc[mt][nt2][half * 2 + 0] + biasrow[n];
                float v1 = acc[mt][nt2][half * 2 + 1] + biasrow[n + 1];
                if (G1) {
                    v0 = __uint_as_float(cvt_tf32(fmaxf(v0, 0.f)));
                    v1 = __uint_as_float(cvt_tf32(fmaxf(v1, 0.f)));
                } else {
                    v0 *= gate;
                    v1 *= gate;
                }
                *(float2*)(outbuf + rowoff + n) = make_float2(v0, v1);
            }
        }
    }
}

// ---------------- Combine: out[t] = y[pair0] + y[pair1] ----------------
__global__ void combine_kernel(float* __restrict__ out) {
    int t = blockIdx.x;
    int i = threadIdx.x;
    int p0 = g_pair[2 * t + 0];
    int p1 = g_pair[2 * t + 1];
    float4 a = ((const float4*)(g_ybuf + (size_t)p0 * D_DIM))[i];
    float4 b = ((const float4*)(g_ybuf + (size_t)p1 * D_DIM))[i];
    float4 r;
    r.x = a.x + b.x; r.y = a.y + b.y; r.z = a.z + b.z; r.w = a.w + b.w;
    ((float4*)(out + (size_t)t * D_DIM))[i] = r;
}

extern "C" void kernel_launch(void* const* d_in, const int* in_sizes, int n_in,
                              void* d_out, int out_size) {
    const float* x     = (const float*)d_in[0];
    const float* noise = (const float*)d_in[1];
    const float* Wr    = (const float*)d_in[2];
    const float* br    = (const float*)d_in[3];
    const float* Wn    = (const float*)d_in[4];
    const float* bn    = (const float*)d_in[5];
    const float* W1    = (const float*)d_in[6];
    const float* b1    = (const float*)d_in[7];
    const float* W2    = (const float*)d_in[8];
    const float* b2    = (const float*)d_in[9];
    float* out = (float*)d_out;

    float* final_out  = out;                               // [B,S,D]
    float* gating_out = out + (size_t)T_TOK * D_DIM;       // [B,S,E]

    zero_counts_kernel<<<1, 32>>>();
    router_kernel<<<512, 256>>>(x, noise, Wr, br, Wn, bn, gating_out);
    tile_sched_kernel<<<1, 32>>>();

    {
        dim3 grid(H_DIM / 128, MAXTILE);
        moe_gemm<true><<<grid, 256>>>(W1, b1);
    }
    {
        dim3 grid(D_DIM / 128, MAXTILE);
        moe_gemm<false><<<grid, 256>>>(W2, b2);
    }
    combine_kernel<<<T_TOK, 256>>>(final_out);
}